// round 3
// baseline (speedup 1.0000x reference)
#include <cuda_runtime.h>
#include <cuda_bf16.h>
#include <cstdint>

#define VOCAB 100000
#define EMB   128
#define NTOK  (4096 * 200)

// 51.2 MB scratch: transposed embedding table [VOCAB, EMB], row-contiguous.
__device__ float g_table[(size_t)VOCAB * EMB];

// ---------------------------------------------------------------------------
// Kernel 1: tiled transpose W[EMB, VOCAB] -> g_table[VOCAB, EMB]
// 32x32 tiles, +1 padding to kill smem bank conflicts.
// Grid: (VOCAB/32, EMB/32) = (3125, 4), block (32, 8).
// ---------------------------------------------------------------------------
__global__ void transpose_kernel(const float* __restrict__ W) {
    __shared__ float tile[32][33];

    const int v0 = blockIdx.x * 32;
    const int e0 = blockIdx.y * 32;

    const int tx = threadIdx.x;
    const int ty = threadIdx.y;

    // Coalesced read along VOCAB (contiguous in W rows)
    const int v = v0 + tx;
#pragma unroll
    for (int i = 0; i < 32; i += 8) {
        tile[ty + i][tx] = W[(size_t)(e0 + ty + i) * VOCAB + v];
    }
    __syncthreads();

    // Coalesced write along EMB (contiguous in table rows)
    const int e = e0 + tx;
#pragma unroll
    for (int i = 0; i < 32; i += 8) {
        g_table[(size_t)(v0 + ty + i) * EMB + e] = tile[tx][ty + i];
    }
}

// ---------------------------------------------------------------------------
// Kernel 2: fused gather + bias + L2 normalize.
// One warp per token: lane l loads float4 #l of the 128-float row (512 B,
// fully coalesced). Warp shfl reduction for sum of squares. Streaming store
// (st.global.cs) for the 419 MB output so the L2-resident table survives.
// ---------------------------------------------------------------------------
__global__ void __launch_bounds__(256) gather_norm_kernel(
    const int* __restrict__ x,
    const float* __restrict__ bias,
    float* __restrict__ out)
{
    const int gwarp = (blockIdx.x * 256 + threadIdx.x) >> 5;
    const int lane  = threadIdx.x & 31;
    if (gwarp >= NTOK) return;

    const int idx = __ldg(&x[gwarp]);

    const float4* __restrict__ row = reinterpret_cast<const float4*>(
        g_table + (size_t)idx * EMB);
    float4 v = row[lane];

    const float4 bb = reinterpret_cast<const float4*>(bias)[lane];
    v.x += bb.x; v.y += bb.y; v.z += bb.z; v.w += bb.w;

    float s = v.x * v.x + v.y * v.y + v.z * v.z + v.w * v.w;
#pragma unroll
    for (int off = 16; off; off >>= 1)
        s += __shfl_xor_sync(0xffffffffu, s, off);

    // matches torch F.normalize: e / max(||e||, eps), eps = 1e-12
    const float inv = 1.0f / fmaxf(sqrtf(s), 1e-12f);
    v.x *= inv; v.y *= inv; v.z *= inv; v.w *= inv;

    float4* __restrict__ orow = reinterpret_cast<float4*>(out) +
                                (size_t)gwarp * 32 + lane;
    __stcs(orow, v);  // streaming store: don't pollute L2
}

// ---------------------------------------------------------------------------
extern "C" void kernel_launch(void* const* d_in, const int* in_sizes, int n_in,
                              void* d_out, int out_size) {
    const int*   x = (const int*)d_in[0];   // [4096, 200] int32
    const float* W = (const float*)d_in[1]; // [128, 100000] f32
    const float* b = (const float*)d_in[2]; // [128] f32
    float* out = (float*)d_out;             // [4096, 200, 128] f32

    // 1) Transpose W into L2-resident scratch table
    dim3 tgrid(VOCAB / 32, EMB / 32);
    dim3 tblock(32, 8);
    transpose_kernel<<<tgrid, tblock>>>(W);

    // 2) Gather + bias + normalize: 1 warp/token, 8 tokens/block
    const int nblocks = NTOK / 8;  // 819200 / 8 = 102400
    gather_norm_kernel<<<nblocks, 256>>>(x, b, out);
}

// round 6
// speedup vs baseline: 1.5223x; 1.5223x over previous
#include <cuda_runtime.h>
#include <cuda_bf16.h>
#include <cstdint>

#define VOCAB 100000
#define EMB   128
#define NTOK  (4096 * 200)

// 51.2 MB scratch: pre-normalized embedding table [VOCAB, EMB], row-contiguous.
// Row v = (W.T[v] + b) / max(||W.T[v] + b||, 1e-12)
__device__ float g_table[(size_t)VOCAB * EMB];

// ---------------------------------------------------------------------------
// Kernel 1: fused transpose + bias + L2-normalize.
// One block owns 32 vocab entries: loads W[0:128][v0:v0+32] (128x32 tile),
// computes per-column norms, writes 32 normalized rows of g_table.
// Grid: VOCAB/32 = 3125 blocks, 256 threads.
// ---------------------------------------------------------------------------
__global__ void __launch_bounds__(256) transpose_norm_kernel(
    const float* __restrict__ W,
    const float* __restrict__ bias)
{
    __shared__ float tile[128][33];   // +1 pad: conflict-free col reads
    __shared__ float bsm[128];
    __shared__ float inv[32];

    const int tid = threadIdx.x;
    const int v0  = blockIdx.x * 32;

    if (tid < 128) bsm[tid] = bias[tid];

    // Load 128x32 tile: consecutive threads sweep vocab (contiguous in W rows)
#pragma unroll
    for (int i = 0; i < 16; i++) {
        const int e = (tid + i * 256) >> 5;
        const int v = tid & 31;
        tile[e][v] = W[(size_t)e * VOCAB + v0 + v];
    }
    __syncthreads();

    // Per-column sum of squares of (tile + bias). 8 warps x 4 columns each.
    const int wid  = tid >> 5;
    const int lane = tid & 31;
#pragma unroll
    for (int j = 0; j < 4; j++) {
        const int c = wid * 4 + j;
        float s = 0.f;
#pragma unroll
        for (int k = 0; k < 4; k++) {
            const int e = lane + k * 32;
            const float t = tile[e][c] + bsm[e];
            s += t * t;
        }
#pragma unroll
        for (int off = 16; off; off >>= 1)
            s += __shfl_xor_sync(0xffffffffu, s, off);
        if (lane == 0)
            inv[c] = 1.0f / fmaxf(sqrtf(s), 1e-12f);
    }
    __syncthreads();

    // Write 32 normalized rows [v][0:128]: consecutive threads sweep emb
    // (contiguous 512B per row, 2 rows per 256-thread pass).
#pragma unroll
    for (int i = 0; i < 16; i++) {
        const int idx = tid + i * 256;
        const int v = idx >> 7;
        const int e = idx & 127;
        g_table[(size_t)(v0 + v) * EMB + e] = (tile[e][v] + bsm[e]) * inv[v];
    }
}

// ---------------------------------------------------------------------------
// Kernel 2: pure gather-copy, 4 tokens per warp for MLP=4.
// Lane l moves float4 #l of each 512B row. Streaming stores keep the
// L2-resident table from being evicted by the 419MB output stream.
// ---------------------------------------------------------------------------
__global__ void __launch_bounds__(256) gather_kernel(
    const int* __restrict__ x,
    float* __restrict__ out)
{
    const int warp = (blockIdx.x * 256 + threadIdx.x) >> 5;
    const int lane = threadIdx.x & 31;
    const int t0   = warp * 4;          // 4 consecutive tokens per warp

    // 4 independent index loads (uniform per warp -> broadcast)
    const int i0 = __ldg(&x[t0 + 0]);
    const int i1 = __ldg(&x[t0 + 1]);
    const int i2 = __ldg(&x[t0 + 2]);
    const int i3 = __ldg(&x[t0 + 3]);

    const float4* __restrict__ tab = reinterpret_cast<const float4*>(g_table);

    // 4 independent 512B row reads in flight
    float4 v0 = tab[(size_t)i0 * 32 + lane];
    float4 v1 = tab[(size_t)i1 * 32 + lane];
    float4 v2 = tab[(size_t)i2 * 32 + lane];
    float4 v3 = tab[(size_t)i3 * 32 + lane];

    float4* __restrict__ o = reinterpret_cast<float4*>(out) + (size_t)t0 * 32 + lane;
    __stcs(o +  0, v0);
    __stcs(o + 32, v1);
    __stcs(o + 64, v2);
    __stcs(o + 96, v3);
}

// ---------------------------------------------------------------------------
extern "C" void kernel_launch(void* const* d_in, const int* in_sizes, int n_in,
                              void* d_out, int out_size) {
    const int*   x = (const int*)d_in[0];   // [4096, 200] int32
    const float* W = (const float*)d_in[1]; // [128, 100000] f32
    const float* b = (const float*)d_in[2]; // [128] f32
    float* out = (float*)d_out;             // [4096, 200, 128] f32

    // 1) Build pre-normalized table (transpose + bias + L2 norm)
    transpose_norm_kernel<<<VOCAB / 32, 256>>>(W, b);

    // 2) Pure gather: 4 tokens/warp, 8 warps/block
    const int nwarps  = NTOK / 4;           // 204800
    const int nblocks = nwarps / 8;         // 25600
    gather_kernel<<<nblocks, 256>>>(x, out);
}